// round 15
// baseline (speedup 1.0000x reference)
#include <cuda_runtime.h>
#include <cstdint>
#include <utility>

// out[B,18] = Theta(x)[B,1330] @ (big_xi*mask)[1330,18]
// mma.sync tf32 m16n8k8. K padded to 1408 = 11 chunks x 128.
// Theta built from REGISTER x, compile-time-unrolled monomials (no LDS in build).
// Warp layout: 4 m-groups (32 rows) x 2 K-halves (8 k-steps each).
// B fragments read DIRECTLY from gmem (__ldg, L1/L2-resident) at mma time:
// no smem staging for B -> 24 KB/chunk less l1tex traffic.

typedef unsigned int u32;

#define NVARS    18
#define KPAD     1408
#define NCHUNK   11
#define KSTEPS   16          // k-steps (of 8) per chunk
#define NTILES   3           // N=24 as 3 x n8
#define MTILE    128
#define THREADS  256
#define TSTRIDE  132         // theta row stride (floats): STS.128/LDS.32 conflict-free
#define RSTRIDE  25          // reduction buffer per-row stride (floats), conflict-free

// ---- compile-time monomial triple for index p: i | j<<5 | k<<10 (18 = one) --
__host__ __device__ constexpr u32 tab_at(int p) {
    if (p == 0) return 18u | (18u << 5) | (18u << 10);
    int q = 1;
    for (int i = 0; i < 18; i++)
        if (q++ == p) return (u32)i | (18u << 5) | (18u << 10);
    for (int i = 0; i < 18; i++)
        for (int j = i; j < 18; j++)
            if (q++ == p) return (u32)i | ((u32)j << 5) | (18u << 10);
    for (int i = 0; i < 18; i++)
        for (int j = i; j < 18; j++)
            for (int k = j; k < 18; k++)
                if (q++ == p) return (u32)i | ((u32)j << 5) | ((u32)k << 10);
    return 18u | (18u << 5) | (18u << 10);   // padding
}

// Prepacked tf32 B fragments: [kstep 176][ntile 3][lane 32][2] floats
__device__ __align__(16) float g_Bfrag[176 * NTILES * 32 * 2];

__device__ __forceinline__ u32 tf32_bits(float f) {
    u32 u;
    asm("cvt.rna.tf32.f32 %0, %1;" : "=r"(u) : "f"(f));
    return u;
}

__device__ __forceinline__ void mma_tf32(float* d, u32 a0, u32 a1, u32 a2, u32 a3,
                                         u32 b0, u32 b1) {
    asm volatile(
        "mma.sync.aligned.m16n8k8.row.col.f32.tf32.tf32.f32 "
        "{%0,%1,%2,%3}, {%4,%5,%6,%7}, {%8,%9}, {%0,%1,%2,%3};"
        : "+f"(d[0]), "+f"(d[1]), "+f"(d[2]), "+f"(d[3])
        : "r"(a0), "r"(a1), "r"(a2), "r"(a3), "r"(b0), "r"(b1));
}

// ---------------- prep: pack W into per-lane tf32 B fragments ----------------
// m16n8k8.row.col B frag: b0 = B[k = 8s + (lane&3)][n = (lane>>2) + 8t], b1: k+4.
__global__ void prep_bfrag(const float* __restrict__ xi, const float* __restrict__ mk) {
    int idx = blockIdx.x * blockDim.x + threadIdx.x;
    if (idx >= 176 * NTILES * 32 * 2) return;
    int e    = idx & 1;
    int lane = (idx >> 1) & 31;
    int st   = idx >> 6;           // s*3 + t
    int t    = st % 3;
    int s    = st / 3;
    int k = 8 * s + (lane & 3) + 4 * e;
    int n = (lane >> 2) + 8 * t;
    float v = 0.f;
    if (k < 1330 && n < NVARS) v = xi[k * NVARS + n] * mk[k * NVARS + n];
    g_Bfrag[idx] = __uint_as_float(tf32_bits(v));
}

// ---------------- compile-time theta build ----------------------------------
template<int SEG, int P>
__device__ __forceinline__ void mono_step(u32* __restrict__ trow,
                                          const float (&x)[19],
                                          u32 (&v)[4]) {
    if constexpr (((P >> 6) & 1) == SEG) {
        float t;
        if constexpr (P >= 1330) {
            t = 0.0f;
        } else if constexpr (P == 0) {
            t = 1.0f;
        } else {
            constexpr u32 e = tab_at(P);
            constexpr int i = e & 31, j = (e >> 5) & 31, k = (e >> 10) & 31;
            if constexpr (j == 18)       t = x[i];
            else if constexpr (k == 18)  t = x[i] * x[j];
            else                         t = (x[i] * x[j]) * x[k];
        }
        v[P & 3] = tf32_bits(t);
        if constexpr ((P & 3) == 3) {
            *(uint4*)(trow + (P & 127) - 3) = make_uint4(v[0], v[1], v[2], v[3]);
        }
    }
}

template<int SEG, int C, size_t... PP>
__device__ __forceinline__ void build_chunk(u32* __restrict__ trow,
                                            const float (&x)[19],
                                            std::index_sequence<PP...>) {
    u32 v[4];
    (mono_step<SEG, C * 128 + (int)PP>(trow, x, v), ...);
}

// ---------------- per-chunk body ---------------------------------------------
// smem layout: theta only
#define OFF_TH   0
#define SMEM_TOT (OFF_TH + MTILE * TSTRIDE * 4)          // 67584 B
// reduction buffer overlays theta area after the last chunk: 128*RSTRIDE*4 = 12.8KB

template<int C>
__device__ __forceinline__ void do_chunk(char* smem, const float (&x)[19],
                                         int tid, int lane, int mw, int kh, int seg,
                                         float (&d)[2][NTILES][4]) {
    u32* theta = (u32*)(smem + OFF_TH);
    const int row = tid & 127;
    const int g   = lane >> 2;
    const int cc  = lane & 3;

    // build this thread's 64-slot half of the theta tile (registers -> STS.128)
    {
        u32* trow = theta + row * TSTRIDE;
        if (seg == 0) build_chunk<0, C>(trow, x, std::make_index_sequence<128>{});
        else          build_chunk<1, C>(trow, x, std::make_index_sequence<128>{});
    }
    __syncthreads();

    // mma: warp owns rows [32*mw, 32*mw+32) (2 m-tiles), k-steps [8*kh, 8*kh+8)
    // B fragments read straight from gmem (L1/L2 resident, coalesced 256B/load).
    {
        const u32* A0 = theta + (32 * mw + g) * TSTRIDE;   // tile0 row g
        const uint2* Bg = (const uint2*)g_Bfrag + C * (KSTEPS * NTILES * 32) + lane;
        #pragma unroll
        for (int s = 0; s < 8; ++s) {
            const int st = 8 * kh + s;
            const int ks = st * 8 + cc;
            u32 a00 = A0[ks],                    a01 = A0[8 * TSTRIDE + ks];
            u32 a02 = A0[ks + 4],                a03 = A0[8 * TSTRIDE + ks + 4];
            u32 a10 = A0[16 * TSTRIDE + ks],     a11 = A0[24 * TSTRIDE + ks];
            u32 a12 = A0[16 * TSTRIDE + ks + 4], a13 = A0[24 * TSTRIDE + ks + 4];
            const uint2* bp = Bg + (st * NTILES) * 32;
            uint2 b0 = __ldg(bp);
            uint2 b1 = __ldg(bp + 32);
            uint2 b2 = __ldg(bp + 64);
            mma_tf32(d[0][0], a00, a01, a02, a03, b0.x, b0.y);
            mma_tf32(d[0][1], a00, a01, a02, a03, b1.x, b1.y);
            mma_tf32(d[0][2], a00, a01, a02, a03, b2.x, b2.y);
            mma_tf32(d[1][0], a10, a11, a12, a13, b0.x, b0.y);
            mma_tf32(d[1][1], a10, a11, a12, a13, b1.x, b1.y);
            mma_tf32(d[1][2], a10, a11, a12, a13, b2.x, b2.y);
        }
    }
    __syncthreads();
}

template<size_t... CC>
__device__ __forceinline__ void do_all(char* smem, const float (&x)[19],
                                       int tid, int lane, int mw, int kh, int seg,
                                       float (&d)[2][NTILES][4],
                                       std::index_sequence<CC...>) {
    (do_chunk<(int)CC>(smem, x, tid, lane, mw, kh, seg, d), ...);
}

// ---------------- main kernel ------------------------------------------------
__global__ __launch_bounds__(THREADS, 2)
void vindy_mma_kernel(const float* __restrict__ z,
                      const float* __restrict__ betas,
                      float* __restrict__ out,
                      int rows)
{
    extern __shared__ __align__(16) char smem[];
    const int tid  = threadIdx.x;
    const int wid  = tid >> 5;
    const int lane = tid & 31;
    const int seg  = tid >> 7;
    const int mw   = wid & 3;        // m-group: rows [32*mw, 32*mw+32)
    const int kh   = wid >> 2;       // k-half: steps [8*kh, 8*kh+8)

    // load this thread's row x into registers (both segs load the same row)
    float x[19];
    {
        int grow = blockIdx.x * MTILE + (tid & 127);
        if (grow > rows - 1) grow = rows - 1;
        const float4* zr = (const float4*)(z + (size_t)grow * 16);
        float4 a = zr[0], b = zr[1], c = zr[2], d = zr[3];
        x[0] = a.x;  x[1] = a.y;  x[2]  = a.z;  x[3]  = a.w;
        x[4] = b.x;  x[5] = b.y;  x[6]  = b.z;  x[7]  = b.w;
        x[8] = c.x;  x[9] = c.y;  x[10] = c.z;  x[11] = c.w;
        x[12] = d.x; x[13] = d.y; x[14] = d.z;  x[15] = d.w;
        const float2 bb = *(const float2*)(betas + (size_t)grow * 2);
        x[16] = bb.x; x[17] = bb.y; x[18] = 1.0f;
    }

    float d[2][NTILES][4] = {};

    do_all(smem, x, tid, lane, mw, kh, seg, d,
           std::make_index_sequence<NCHUNK>{});

    // ---- cross-K reduction: kh=1 warps dump partials, kh=0 warps add ----
    {
        float* red = (float*)(smem + OFF_TH);   // reuse theta area (post-sync)
        if (kh == 1) {
            float* r = red + (mw * 32 + lane) * RSTRIDE;
            #pragma unroll
            for (int mt = 0; mt < 2; ++mt)
                #pragma unroll
                for (int t = 0; t < NTILES; ++t)
                    #pragma unroll
                    for (int e = 0; e < 4; ++e)
                        r[(mt * NTILES + t) * 4 + e] = d[mt][t][e];
        }
        __syncthreads();
        if (kh == 0) {
            const float* r = red + (mw * 32 + lane) * RSTRIDE;
            #pragma unroll
            for (int mt = 0; mt < 2; ++mt)
                #pragma unroll
                for (int t = 0; t < NTILES; ++t)
                    #pragma unroll
                    for (int e = 0; e < 4; ++e)
                        d[mt][t][e] += r[(mt * NTILES + t) * 4 + e];
        }
    }

    // ---- epilogue (kh=0 warps): frag c0=(r,2cc) c1=(r,2cc+1) c2/c3 = +8 row --
    if (kh == 0) {
        const int g  = lane >> 2;
        const int cc = lane & 3;
        #pragma unroll
        for (int mt = 0; mt < 2; ++mt) {
            const int r0 = blockIdx.x * MTILE + 32 * mw + 16 * mt + g;
            const int r1 = r0 + 8;
            if (r0 < rows) {
                float* o = out + (size_t)r0 * NVARS;
                *(float2*)(o + 2 * cc)     = make_float2(d[mt][0][0], d[mt][0][1]);
                *(float2*)(o + 2 * cc + 8) = make_float2(d[mt][1][0], d[mt][1][1]);
                if (cc == 0) *(float2*)(o + 16) = make_float2(d[mt][2][0], d[mt][2][1]);
            }
            if (r1 < rows) {
                float* o = out + (size_t)r1 * NVARS;
                *(float2*)(o + 2 * cc)     = make_float2(d[mt][0][2], d[mt][0][3]);
                *(float2*)(o + 2 * cc + 8) = make_float2(d[mt][1][2], d[mt][1][3]);
                if (cc == 0) *(float2*)(o + 16) = make_float2(d[mt][2][2], d[mt][2][3]);
            }
        }
    }
}

extern "C" void kernel_launch(void* const* d_in, const int* in_sizes, int n_in,
                              void* d_out, int out_size)
{
    const float* z      = (const float*)d_in[0];
    const float* betas  = (const float*)d_in[1];
    const float* big_xi = (const float*)d_in[2];
    const float* mask   = (const float*)d_in[3];
    float* out = (float*)d_out;

    const int rows = in_sizes[0] / 16;   // z is [rows, 16]

    prep_bfrag<<<(176 * NTILES * 64 + 255) / 256, 256>>>(big_xi, mask);

    cudaFuncSetAttribute(vindy_mma_kernel,
                         cudaFuncAttributeMaxDynamicSharedMemorySize, SMEM_TOT);
    const int grid = (rows + MTILE - 1) / MTILE;
    vindy_mma_kernel<<<grid, THREADS, SMEM_TOT>>>(z, betas, out, rows);
}